// round 16
// baseline (speedup 1.0000x reference)
#include <cuda_runtime.h>

// SAKE GNN fully fused, one CTA per graph (B=512, M=32, H=128, L=2).
// R16: R15 (3-way warp-specialized pair phase + interleaved WF) with the
//      missing post-pair-phase __syncthreads() restored — fixes the WF
//      overwrite race (builders staging Wh1a while consumers read We2).

#define NB 512
#define NT 1024
typedef unsigned int u32;
typedef unsigned short u16;

// global fragment buffer: 14 big Ws (16384 u32 each) + W_in (2048)
__device__ u32 g_wfrag[14 * 16384 + 2048];
#define WIN_BASE (14 * 16384)

// ---- shared memory layout (u32 word offsets) ----
#define O_HGH 0        // hg split: 32 x 68
#define O_HGL 2176
#define O_MIF 4352     // mi f32: 32 x 132
#define O_MJF 8576     // mj f32: 32 x 132
#define O_AGH 12800    // agg split: 32 x 68
#define O_AGL 14976
#define O_M1H 17152    // m1 split: 2 bufs x 32 x 68
#define O_M1L 21504
#define O_HTH 25856    // h input split: 32 x 8
#define O_HTL 26112
#define O_WF  26368    // W fragments interleaved: 8kt x 16nt x 32lane x 4
#define O_M2TH 42752   // m2 B-frag hi: 2 bufs x (128 cols x 20); also kh scratch
#define O_M2TL 47872
#define O_S   52992    // S selection: 2 bufs x (32 rows x 20)
#define O_D2  54912
#define O_EDGE 55936
#define O_WD  56960
#define O_BE2 57088
#define O_RMASK 57216
#define O_ROFF 57248
#define O_X   57280
#define O_RED 57376
#define O_NE  57392
#define SM_WORDS 57396

// named barrier ids
#define BFULL0  1
#define BEMPTY0 3
#define BM2_0   5
#define BM2E0   7
#define BAGG    9

#define BAR_SYNC(id, n)   asm volatile("bar.sync %0, %1;"   :: "r"(id), "r"(n) : "memory")
#define BAR_ARRIVE(id, n) asm volatile("bar.arrive %0, %1;" :: "r"(id), "r"(n) : "memory")

__device__ __forceinline__ float silu_f(float v) {
    return __fdividef(v, 1.0f + __expf(-v));
}
__device__ __forceinline__ u32 packbf(float x0, float x1) {
    u32 r;
    asm("cvt.rn.bf16x2.f32 %0, %1, %2;" : "=r"(r) : "f"(x1), "f"(x0));
    return r;
}
__device__ __forceinline__ void split2(float x0, float x1, u32& h, u32& l) {
    h = packbf(x0, x1);
    float r0 = x0 - __uint_as_float(h << 16);
    float r1 = x1 - __uint_as_float(h & 0xffff0000u);
    l = packbf(r0, r1);
}
__device__ __forceinline__ float2 ldpair(const u32* Xh, const u32* Xl, int idx) {
    u32 h = Xh[idx], l = Xl[idx];
    float2 v;
    v.x = __uint_as_float(h << 16) + __uint_as_float(l << 16);
    v.y = __uint_as_float(h & 0xffff0000u) + __uint_as_float(l & 0xffff0000u);
    return v;
}
__device__ __forceinline__ void stpair(u32* Xh, u32* Xl, int idx, float v0, float v1) {
    u32 h, l; split2(v0, v1, h, l);
    Xh[idx] = h; Xl[idx] = l;
}

__device__ __forceinline__ void mma4(float d[4], const u32 a[4], u32 b0, u32 b1) {
    asm volatile("mma.sync.aligned.m16n8k16.row.col.f32.bf16.bf16.f32 "
        "{%0,%1,%2,%3}, {%4,%5,%6,%7}, {%8,%9}, {%0,%1,%2,%3};"
        : "+f"(d[0]), "+f"(d[1]), "+f"(d[2]), "+f"(d[3])
        : "r"(a[0]), "r"(a[1]), "r"(a[2]), "r"(a[3]), "r"(b0), "r"(b1));
}

__device__ __forceinline__ u32 smaddr(const void* p) {
    return (u32)__cvta_generic_to_shared(p);
}
#define LDSM4(d, a) \
    asm volatile("ldmatrix.sync.aligned.m8n8.x4.shared.b16 {%0,%1,%2,%3}, [%4];" \
        : "=r"((d)[0]), "=r"((d)[1]), "=r"((d)[2]), "=r"((d)[3]) : "r"(a))

// 3-term GEMM, TWO n-tiles/warp, kt range [kt0,kt1); WF interleaved.
__device__ __forceinline__ void gemm_mma2n(const u32* Xh, const u32* Xl, int rs,
                                           const u32* sWF, int r0, int ntb,
                                           int lane, int kt0, int kt1,
                                           float D[2][4]) {
    int t = lane >> 3, rowin = lane & 7;
    int off = (r0 + ((t & 1) << 3) + rowin) * rs + ((t >> 1) << 2);
    u32 baseH = smaddr(Xh + off);
    u32 baseL = smaddr(Xl + off);
    #pragma unroll 1
    for (int kt = kt0; kt < kt1; kt++) {
        u32 ah[4], al[4];
        LDSM4(ah, baseH + kt * 32);
        LDSM4(al, baseL + kt * 32);
        #pragma unroll
        for (int t2 = 0; t2 < 2; t2++) {
            uint4 bb = *(const uint4*)(sWF + ((kt * 16 + ntb + t2) * 32 + lane) * 4);
            mma4(D[t2], ah, bb.x, bb.y);
            mma4(D[t2], ah, bb.z, bb.w);
            mma4(D[t2], al, bb.x, bb.y);
        }
    }
}

// consumer pair GEMM: FOUR n-tiles per warp, all 8 kt (rs=68)
__device__ __forceinline__ void gemm_mma4n(const u32* Xh, const u32* Xl,
                                           const u32* sWF, int r0, int ntb,
                                           int lane, float D[4][4]) {
    int t = lane >> 3, rowin = lane & 7;
    int off = (r0 + ((t & 1) << 3) + rowin) * 68 + ((t >> 1) << 2);
    u32 baseH = smaddr(Xh + off);
    u32 baseL = smaddr(Xl + off);
    #pragma unroll 1
    for (int kt = 0; kt < 8; kt++) {
        u32 ah[4], al[4];
        LDSM4(ah, baseH + kt * 32);
        LDSM4(al, baseL + kt * 32);
        #pragma unroll
        for (int t2 = 0; t2 < 4; t2++) {
            uint4 bb = *(const uint4*)(sWF + ((kt * 16 + ntb + t2) * 32 + lane) * 4);
            mma4(D[t2], ah, bb.x, bb.y);
            mma4(D[t2], ah, bb.z, bb.w);
            mma4(D[t2], al, bb.x, bb.y);
        }
    }
}

// combine kh halves via smem scratch; returns true if this warp owns epilogue.
__device__ __forceinline__ bool reduce_kh(float D[2][4], float* scr,
                                          int kh, int rtn, int ntp, int lane) {
    int base = (((rtn << 3) + ntp) * 32 + lane) * 8;
    if (kh) {
        *(float4*)&scr[base]     = make_float4(D[0][0], D[0][1], D[0][2], D[0][3]);
        *(float4*)&scr[base + 4] = make_float4(D[1][0], D[1][1], D[1][2], D[1][3]);
    }
    __syncthreads();
    if (!kh) {
        float4 p0 = *(const float4*)&scr[base];
        float4 p1 = *(const float4*)&scr[base + 4];
        D[0][0] += p0.x; D[0][1] += p0.y; D[0][2] += p0.z; D[0][3] += p0.w;
        D[1][0] += p1.x; D[1][1] += p1.y; D[1][2] += p1.z; D[1][3] += p1.w;
    }
    return !kh;
}

__device__ __forceinline__ void cp16(unsigned saddr, const void* g) {
    asm volatile("cp.async.cg.shared.global [%0], [%1], 16;" :: "r"(saddr), "l"(g));
}
#define CP_COMMIT() asm volatile("cp.async.commit_group;")
#define CP_WAIT0()  asm volatile("cp.async.wait_group 0;" ::: "memory")

__device__ __forceinline__ void stage_cp(const u32* __restrict__ g, u32* s,
                                         int nf4, int tid) {
    unsigned sa = (unsigned)__cvta_generic_to_shared(s);
    for (int v = tid; v < nf4; v += NT)
        cp16(sa + v * 16, g + v * 4);
}
__device__ __forceinline__ void stage_W(const u32* __restrict__ F, u32* WF, int tid) {
    stage_cp(F, WF, 4096, tid);
    CP_COMMIT();
}

// write one f32 value into the hi/lo B-fragment m2 buffers at (col c, edge r)
__device__ __forceinline__ void write_m2t(u32* M2THb, u32* M2TLb, int c, int r, float v) {
    u32 hp = packbf(v, 0.0f);
    float hf = __uint_as_float(hp << 16);
    u32 lp = packbf(v - hf, 0.0f);
    int wi = (c * 20 + (r >> 1)) * 2 + (r & 1);
    ((u16*)M2THb)[wi] = (u16)hp;
    ((u16*)M2TLb)[wi] = (u16)lp;
}

// builder: 512 threads, 16 threads/edge, 8 cols each
__device__ __forceinline__ void build_chunk_p(int e0, int nE, const int* s_edge,
                                              const float* s_d2, const float* miF,
                                              const float* mjF, const float* s_wd,
                                              u32* M1Hb, u32* M1Lb, int tid) {
    int e = tid >> 4;            // 0..31
    int cq = (tid & 15) * 8;     // 8 cols
    int ee = e0 + e;
    int ij = s_edge[ee < nE ? ee : nE - 1];
    int i = ij >> 5, j = ij & 31;
    float dd = s_d2[ij];
    u32 hb[4], lb[4];
    #pragma unroll
    for (int q = 0; q < 2; q++) {
        float4 a = *(const float4*)&miF[i * 132 + cq + 4 * q];
        float4 bb = *(const float4*)&mjF[j * 132 + cq + 4 * q];
        float4 w = *(const float4*)&s_wd[cq + 4 * q];
        float v0 = silu_f(a.x + bb.x + dd * w.x);
        float v1 = silu_f(a.y + bb.y + dd * w.y);
        float v2 = silu_f(a.z + bb.z + dd * w.z);
        float v3 = silu_f(a.w + bb.w + dd * w.w);
        split2(v0, v1, hb[2 * q], lb[2 * q]);
        split2(v2, v3, hb[2 * q + 1], lb[2 * q + 1]);
    }
    *(uint4*)&M1Hb[e * 68 + (cq >> 1)] = make_uint4(hb[0], hb[1], hb[2], hb[3]);
    *(uint4*)&M1Lb[e * 68 + (cq >> 1)] = make_uint4(lb[0], lb[1], lb[2], lb[3]);
}

// build S selection matrix: 256 agg threads, 2 cells each
__device__ __forceinline__ void build_S256(int e0, int nE, const int* s_edge,
                                           u32* Sb, int tid2) {
    int i = tid2 >> 3;
    int epb = (tid2 & 7) * 2;
    #pragma unroll
    for (int q = 0; q < 2; q++) {
        int ep = epb + q;
        int ea = e0 + 2 * ep, eb = ea + 1;
        int ia = (ea < nE) ? (s_edge[ea] >> 5) : -1;
        int ib = (eb < nE) ? (s_edge[eb] >> 5) : -1;
        u32 val = (ia == i ? 0x00003F80u : 0u) | (ib == i ? 0x3F800000u : 0u);
        Sb[i * 20 + ep] = val;
    }
}

// agg: Dagg[4][4] += S @ (m2h + m2l), 4 n-tiles per warp
__device__ __forceinline__ void agg_mma4(const u32* Sp, const u32* m2h,
                                         const u32* m2l, int art, int antb,
                                         int lane, float Dagg[4][4]) {
    int t = lane >> 3, rowin = lane & 7;
    u32 baseS = smaddr(Sp + (art * 16 + ((t & 1) << 3) + rowin) * 20 + ((t >> 1) << 2));
    #pragma unroll
    for (int kt = 0; kt < 2; kt++) {
        u32 a[4];
        LDSM4(a, baseS + kt * 32);
        #pragma unroll
        for (int t2 = 0; t2 < 4; t2++) {
            int cB = (antb + t2) * 8 + (lane >> 2);
            const u32* bh = m2h + cB * 20 + kt * 8 + (lane & 3);
            const u32* bl = m2l + cB * 20 + kt * 8 + (lane & 3);
            mma4(Dagg[t2], a, bh[0], bh[4]);
            mma4(Dagg[t2], a, bl[0], bl[4]);
        }
    }
}

// ================= prep kernel: weights -> interleaved fragment layout ======
__global__ void prep_kernel(const float* __restrict__ We1,
                            const float* __restrict__ We2,
                            const float* __restrict__ Wh1,
                            const float* __restrict__ Wh2,
                            const float* __restrict__ W_out,
                            const float* __restrict__ Wn1,
                            const float* __restrict__ W_in) {
    int y = blockIdx.y;
    int u = blockIdx.x * 256 + threadIdx.x;
    if (y < 14) {
        const float* src;
        if (y < 12) {
            int l = y / 6, w = y % 6;
            switch (w) {
                case 0: src = We1 + l * 257 * 128; break;
                case 1: src = We1 + l * 257 * 128 + 16384; break;
                case 2: src = We2 + l * 16384; break;
                case 3: src = Wh1 + l * 32768; break;
                case 4: src = Wh1 + l * 32768 + 16384; break;
                default: src = Wh2 + l * 16384; break;
            }
        } else {
            src = (y == 12) ? W_out : Wn1;
        }
        int p = u >> 7, c = u & 127;
        float w0 = src[(2 * p) * 128 + c];
        float w1 = src[(2 * p + 1) * 128 + c];
        int kt = p >> 3, pr = p & 7;
        int cpp = pr & 3, reg = pr >> 2;
        int lane = (c & 7) * 4 + cpp;
        int nt = c >> 3;
        int dst = y * 16384 + ((kt * 16 + nt) * 32 + lane) * 4 + reg;
        u32 h, l2; split2(w0, w1, h, l2);
        g_wfrag[dst] = h;
        g_wfrag[dst + 2] = l2;
    } else {
        if (u >= 1024) return;
        int p = u >> 7, c = u & 127;
        float w0 = W_in[(2 * p) * 128 + c];
        float w1 = W_in[(2 * p + 1) * 128 + c];
        int cpp = p & 3, reg = p >> 2;
        int lane = (c & 7) * 4 + cpp;
        int nt = c >> 3;
        int dst = WIN_BASE + ((nt * 32 + lane) * 4 + reg);
        u32 h, l2; split2(w0, w1, h, l2);
        g_wfrag[dst] = h;
        g_wfrag[dst + 2] = l2;
    }
}

// ================================ main kernel ================================
__global__ void __launch_bounds__(NT, 1)
sake_kernel(const float* __restrict__ g_h, const float* __restrict__ g_x,
            const float* __restrict__ b_in,
            const float* __restrict__ We1, const float* __restrict__ be1,
            const float* __restrict__ be2,
            const float* __restrict__ bh1, const float* __restrict__ bh2,
            const float* __restrict__ b_out,
            const float* __restrict__ bn1,
            const float* __restrict__ Wn2, const float* __restrict__ bn2,
            float* __restrict__ g_out)
{
    extern __shared__ u32 smu[];
    u32* HGH = smu + O_HGH;  u32* HGL = smu + O_HGL;
    float* miF = (float*)(smu + O_MIF);
    float* mjF = (float*)(smu + O_MJF);
    u32* AGH = smu + O_AGH;  u32* AGL = smu + O_AGL;
    u32* M1H = smu + O_M1H;  u32* M1L = smu + O_M1L;
    u32* HTH = smu + O_HTH;  u32* HTL = smu + O_HTL;
    u32* WF  = smu + O_WF;
    u32* M2TH = smu + O_M2TH;
    u32* M2TL = smu + O_M2TL;
    float* scrF = (float*)(smu + O_M2TH);   // kh reduction scratch (node GEMMs)
    u32* Sbuf = smu + O_S;
    float* s_d2   = (float*)(smu + O_D2);
    int*   s_edge = (int*)(smu + O_EDGE);
    float* s_wd   = (float*)(smu + O_WD);
    float* s_be2  = (float*)(smu + O_BE2);
    u32*   s_rmask = smu + O_RMASK;
    int*   s_roff  = (int*)(smu + O_ROFF);
    float* s_x    = (float*)(smu + O_X);
    float* s_red  = (float*)(smu + O_RED);
    int*   s_ne   = (int*)(smu + O_NE);

    const int tid  = threadIdx.x;
    const int warp = tid >> 5;          // 0..31
    const int lane = tid & 31;
    const int gid  = lane >> 2;
    const int tig  = lane & 3;
    const int b    = blockIdx.x;
    // node-GEMM mapping: (kh, rtn, ntp)
    const int kh   = warp & 1;
    const int rtn  = (warp >> 1) & 1;
    const int ntp  = warp >> 2;         // 0..7
    const int ntbN = ntp * 2;
    const int rr0  = rtn * 16 + gid;
    const int kt0  = kh ? 4 : 0;
    const int kt1  = kh ? 8 : 4;

    // ---- prologue: x, split h, stage W_in frags ----
    if (tid < 96) s_x[tid] = g_x[b * 96 + tid];
    if (tid < 256) {
        int r = tid >> 3, cp = tid & 7;
        float2 hv = *(const float2*)&g_h[b * 512 + r * 16 + cp * 2];
        u32 h, l; split2(hv.x, hv.y, h, l);
        HTH[r * 8 + cp] = h; HTL[r * 8 + cp] = l;
    }
    stage_cp(g_wfrag + WIN_BASE, WF, 512, tid);
    CP_COMMIT();
    __syncthreads();

    // ---- d2 ----
    for (int p = tid; p < 1024; p += NT) {
        int i = p >> 5, j = p & 31;
        float dx = s_x[i * 3 + 0] - s_x[j * 3 + 0];
        float dy = s_x[i * 3 + 1] - s_x[j * 3 + 1];
        float dz = s_x[i * 3 + 2] - s_x[j * 3 + 2];
        s_d2[p] = dx * dx + dy * dy + dz * dz;
    }
    __syncthreads();

    // ---- adjacency masks: warp w owns node w ----
    {
        bool adj = (s_d2[warp * 32 + lane] < 1.0f) && (lane != warp);
        unsigned m = __ballot_sync(0xffffffffu, adj);
        if (lane == 0) s_rmask[warp] = m;
    }
    CP_WAIT0();
    __syncthreads();

    // ---- hg = h @ W_in + b_in (kh0 warps only; 1 kt) ----
    if (!kh) {
        float D[2][4] = {};
        gemm_mma2n(HTH, HTL, 8, WF, rtn * 16, ntbN, lane, 0, 1, D);
        #pragma unroll
        for (int t2 = 0; t2 < 2; t2++) {
            int cc = (ntbN + t2) * 8 + 2 * tig;
            float b0 = b_in[cc], b1 = b_in[cc + 1];
            stpair(HGH, HGL, rr0 * 68 + (cc >> 1),       D[t2][0] + b0, D[t2][1] + b1);
            stpair(HGH, HGL, (rr0 + 8) * 68 + (cc >> 1), D[t2][2] + b0, D[t2][3] + b1);
        }
    }

    // ---- edge-list scan ----
    __syncthreads();
    if (warp == 0) {
        unsigned m = s_rmask[lane];
        int c = __popc(m);
        int inc = c;
        #pragma unroll
        for (int d = 1; d < 32; d <<= 1) {
            int n = __shfl_up_sync(0xffffffffu, inc, d);
            if (lane >= d) inc += n;
        }
        s_roff[lane] = inc - c;
        if (lane == 31) *s_ne = inc;
    }
    __syncthreads();
    {
        unsigned m = s_rmask[warp];
        if ((m >> lane) & 1u) {
            int pos = s_roff[warp] + __popc(m & ((1u << lane) - 1u));
            s_edge[pos] = (warp << 5) | lane;
        }
    }
    __syncthreads();
    const int nE = *s_ne;
    const int nCh = (nE + 31) >> 5;

    // ---- layers ----
    #pragma unroll 1
    for (int l = 0; l < 2; l++) {
        const u32* F_e1a = g_wfrag + (l * 6 + 0) * 16384;
        const u32* F_e1b = g_wfrag + (l * 6 + 1) * 16384;
        const u32* F_e2  = g_wfrag + (l * 6 + 2) * 16384;
        const u32* F_h1a = g_wfrag + (l * 6 + 3) * 16384;
        const u32* F_h1b = g_wfrag + (l * 6 + 4) * 16384;
        const u32* F_h2  = g_wfrag + (l * 6 + 5) * 16384;
        const float* We1l = We1 + l * (257 * 128);

        // mi = hg @ We1a + be1 -> miF
        stage_W(F_e1a, WF, tid); CP_WAIT0(); __syncthreads();
        {
            float D[2][4] = {};
            gemm_mma2n(HGH, HGL, 68, WF, rtn * 16, ntbN, lane, kt0, kt1, D);
            if (reduce_kh(D, scrF, kh, rtn, ntp, lane)) {
                #pragma unroll
                for (int t2 = 0; t2 < 2; t2++) {
                    int cc = (ntbN + t2) * 8 + 2 * tig;
                    float b0 = be1[l * 128 + cc], b1 = be1[l * 128 + cc + 1];
                    *(float2*)&miF[rr0 * 132 + cc]       = make_float2(D[t2][0] + b0, D[t2][1] + b1);
                    *(float2*)&miF[(rr0 + 8) * 132 + cc] = make_float2(D[t2][2] + b0, D[t2][3] + b1);
                }
            }
        }
        __syncthreads();

        // mj = hg @ We1b -> mjF
        stage_W(F_e1b, WF, tid); CP_WAIT0(); __syncthreads();
        {
            float D[2][4] = {};
            gemm_mma2n(HGH, HGL, 68, WF, rtn * 16, ntbN, lane, kt0, kt1, D);
            if (reduce_kh(D, scrF, kh, rtn, ntp, lane)) {
                #pragma unroll
                for (int t2 = 0; t2 < 2; t2++) {
                    int cc = (ntbN + t2) * 8 + 2 * tig;
                    *(float2*)&mjF[rr0 * 132 + cc]       = make_float2(D[t2][0], D[t2][1]);
                    *(float2*)&mjF[(rr0 + 8) * 132 + cc] = make_float2(D[t2][2], D[t2][3]);
                }
            }
        }
        __syncthreads();

        // stage We2; wd, be2
        stage_W(F_e2, WF, tid);
        if (tid < 128) {
            s_wd[tid]  = We1l[256 * 128 + tid];
            s_be2[tid] = be2[l * 128 + tid];
        }
        CP_WAIT0();
        __syncthreads();

        // ---- pair phase: 3-way warp specialization ----
        if (warp < 16) {
            // BUILDERS (512 thr): m1 chunks
            #pragma unroll 1
            for (int c = 0; c < nCh; c++) {
                const int buf = c & 1;
                if (c >= 2) BAR_SYNC(BEMPTY0 + buf, 768);
                build_chunk_p(c * 32, nE, s_edge, s_d2, miF, mjF, s_wd,
                              M1H + buf * 2176, M1L + buf * 2176, tid);
                BAR_ARRIVE(BFULL0 + buf, 768);
            }
        } else if (warp < 24) {
            // CONSUMERS (256 thr): pair GEMM, 4 n-tiles/warp
            const int cw   = warp - 16;
            const int crt  = cw & 1;
            const int cntb = (cw >> 1) * 4;
            const int cr0  = crt * 16 + gid;
            #pragma unroll 1
            for (int c = 0; c < nCh; c++) {
                const int buf = c & 1;
                BAR_SYNC(BFULL0 + buf, 768);
                if (c >= 2) BAR_SYNC(BM2E0 + buf, 512);
                float D[4][4] = {};
                gemm_mma4n(M1H + buf * 2176, M1L + buf * 2176, WF,
                           crt * 16, cntb, lane, D);
                u32* m2h = M2TH + buf * 2560;
                u32* m2l = M2TL + buf * 2560;
                #pragma unroll
                for (int t2 = 0; t2 < 4; t2++) {
                    int cc = (cntb + t2) * 8 + 2 * tig;
                    float b0 = s_be2[cc], b1 = s_be2[cc + 1];
                    write_m2t(m2h, m2l, cc,     cr0,     silu_f(D[t2][0] + b0));
                    write_m2t(m2h, m2l, cc + 1, cr0,     silu_f(D[t2][1] + b1));
                    write_m2t(m2h, m2l, cc,     cr0 + 8, silu_f(D[t2][2] + b0));
                    write_m2t(m2h, m2l, cc + 1, cr0 + 8, silu_f(D[t2][3] + b1));
                }
                BAR_ARRIVE(BM2_0 + buf, 512);
                if (c < nCh - 2) BAR_ARRIVE(BEMPTY0 + buf, 768);
            }
        } else {
            // AGG warps (256 thr): build S + aggregate via MMA
            const int aw   = warp - 24;
            const int art  = aw & 1;
            const int antb = (aw >> 1) * 4;
            const int ar0  = art * 16 + gid;
            const int tid2 = tid - 768;
            float Dagg[4][4] = {};
            #pragma unroll 1
            for (int c = 0; c < nCh; c++) {
                const int buf = c & 1;
                build_S256(c * 32, nE, s_edge, Sbuf + buf * 640, tid2);
                BAR_SYNC(BAGG, 256);
                BAR_SYNC(BM2_0 + buf, 512);
                agg_mma4(Sbuf + buf * 640, M2TH + buf * 2560, M2TL + buf * 2560,
                         art, antb, lane, Dagg);
                if (c < nCh - 2) BAR_ARRIVE(BM2E0 + buf, 512);
            }
            // write agg -> AG split arrays (ordered by the __syncthreads below)
            #pragma unroll
            for (int t2 = 0; t2 < 4; t2++) {
                int cc = (antb + t2) * 8 + 2 * tig;
                stpair(AGH, AGL, ar0 * 68 + (cc >> 1),       Dagg[t2][0], Dagg[t2][1]);
                stpair(AGH, AGL, (ar0 + 8) * 68 + (cc >> 1), Dagg[t2][2], Dagg[t2][3]);
            }
        }
        __syncthreads();   // ALL groups done with WF(We2)/m2/AG before restaging

        stage_W(F_h1a, WF, tid);
        CP_WAIT0();
        __syncthreads();

        // u = silu(hg @ Wh1a + agg @ Wh1b + bh1) -> M1 (split, buf0)
        {
            float D[2][4] = {};
            gemm_mma2n(HGH, HGL, 68, WF, rtn * 16, ntbN, lane, kt0, kt1, D);
            __syncthreads();
            stage_W(F_h1b, WF, tid);
            CP_WAIT0();
            __syncthreads();
            gemm_mma2n(AGH, AGL, 68, WF, rtn * 16, ntbN, lane, kt0, kt1, D);
            if (reduce_kh(D, scrF, kh, rtn, ntp, lane)) {
                #pragma unroll
                for (int t2 = 0; t2 < 2; t2++) {
                    int cc = (ntbN + t2) * 8 + 2 * tig;
                    float b0 = bh1[l * 128 + cc], b1 = bh1[l * 128 + cc + 1];
                    stpair(M1H, M1L, rr0 * 68 + (cc >> 1),
                           silu_f(D[t2][0] + b0), silu_f(D[t2][1] + b1));
                    stpair(M1H, M1L, (rr0 + 8) * 68 + (cc >> 1),
                           silu_f(D[t2][2] + b0), silu_f(D[t2][3] + b1));
                }
            }
        }
        __syncthreads();

        // hg += u @ Wh2 + bh2
        stage_W(F_h2, WF, tid); CP_WAIT0(); __syncthreads();
        {
            float D[2][4] = {};
            gemm_mma2n(M1H, M1L, 68, WF, rtn * 16, ntbN, lane, kt0, kt1, D);
            if (reduce_kh(D, scrF, kh, rtn, ntp, lane)) {
                #pragma unroll
                for (int t2 = 0; t2 < 2; t2++) {
                    int cc = (ntbN + t2) * 8 + 2 * tig;
                    float b0 = bh2[l * 128 + cc], b1 = bh2[l * 128 + cc + 1];
                    float2 h0 = ldpair(HGH, HGL, rr0 * 68 + (cc >> 1));
                    stpair(HGH, HGL, rr0 * 68 + (cc >> 1),
                           h0.x + D[t2][0] + b0, h0.y + D[t2][1] + b1);
                    float2 h1 = ldpair(HGH, HGL, (rr0 + 8) * 68 + (cc >> 1));
                    stpair(HGH, HGL, (rr0 + 8) * 68 + (cc >> 1),
                           h1.x + D[t2][2] + b0, h1.y + D[t2][3] + b1);
                }
            }
        }
        __syncthreads();
    }

    // ---- head: ho = hg @ W_out + b_out -> M1 (split, buf0) ----
    stage_W(g_wfrag + 12 * 16384, WF, tid); CP_WAIT0(); __syncthreads();
    {
        float D[2][4] = {};
        gemm_mma2n(HGH, HGL, 68, WF, rtn * 16, ntbN, lane, kt0, kt1, D);
        if (reduce_kh(D, scrF, kh, rtn, ntp, lane)) {
            #pragma unroll
            for (int t2 = 0; t2 < 2; t2++) {
                int cc = (ntbN + t2) * 8 + 2 * tig;
                float b0 = b_out[cc], b1 = b_out[cc + 1];
                stpair(M1H, M1L, rr0 * 68 + (cc >> 1),       D[t2][0] + b0, D[t2][1] + b1);
                stpair(M1H, M1L, (rr0 + 8) * 68 + (cc >> 1), D[t2][2] + b0, D[t2][3] + b1);
            }
        }
    }
    __syncthreads();

    // t1 = silu(ho @ Wn1 + bn1) -> miF (f32)
    stage_W(g_wfrag + 13 * 16384, WF, tid); CP_WAIT0(); __syncthreads();
    {
        float D[2][4] = {};
        gemm_mma2n(M1H, M1L, 68, WF, rtn * 16, ntbN, lane, kt0, kt1, D);
        if (reduce_kh(D, scrF, kh, rtn, ntp, lane)) {
            #pragma unroll
            for (int t2 = 0; t2 < 2; t2++) {
                int cc = (ntbN + t2) * 8 + 2 * tig;
                float b0 = bn1[cc], b1 = bn1[cc + 1];
                *(float2*)&miF[rr0 * 132 + cc] =
                    make_float2(silu_f(D[t2][0] + b0), silu_f(D[t2][1] + b1));
                *(float2*)&miF[(rr0 + 8) * 132 + cc] =
                    make_float2(silu_f(D[t2][2] + b0), silu_f(D[t2][3] + b1));
            }
        }
    }
    __syncthreads();

    // ---- out[b] = (colsum t1) . Wn2 + 32*bn2 ----
    float part = 0.0f;
    if (tid < 128) {
        int c = tid;
        float s = 0.0f;
        #pragma unroll 1
        for (int i = 0; i < 32; i++) s += miF[i * 132 + c];
        part = s * Wn2[c];
    }
    #pragma unroll
    for (int off = 16; off > 0; off >>= 1)
        part += __shfl_down_sync(0xffffffffu, part, off);
    if (warp < 4 && lane == 0) s_red[warp] = part;
    __syncthreads();
    if (tid == 0)
        g_out[b] = s_red[0] + s_red[1] + s_red[2] + s_red[3] + 32.0f * bn2[0];
}

extern "C" void kernel_launch(void* const* d_in, const int* in_sizes, int n_in,
                              void* d_out, int out_size) {
    const float* g_h   = (const float*)d_in[0];
    const float* g_x   = (const float*)d_in[1];
    const float* W_in  = (const float*)d_in[3];
    const float* b_in  = (const float*)d_in[4];
    const float* We1   = (const float*)d_in[5];
    const float* be1   = (const float*)d_in[6];
    const float* We2   = (const float*)d_in[7];
    const float* be2   = (const float*)d_in[8];
    const float* Wh1   = (const float*)d_in[9];
    const float* bh1   = (const float*)d_in[10];
    const float* Wh2   = (const float*)d_in[11];
    const float* bh2   = (const float*)d_in[12];
    const float* W_out = (const float*)d_in[13];
    const float* b_out = (const float*)d_in[14];
    const float* Wn1   = (const float*)d_in[15];
    const float* bn1   = (const float*)d_in[16];
    const float* Wn2   = (const float*)d_in[17];
    const float* bn2   = (const float*)d_in[18];
    float* out = (float*)d_out;

    prep_kernel<<<dim3(32, 15), 256>>>(We1, We2, Wh1, Wh2, W_out, Wn1, W_in);

    const int smem_bytes = SM_WORDS * 4;
    cudaFuncSetAttribute(sake_kernel, cudaFuncAttributeMaxDynamicSharedMemorySize,
                         smem_bytes);
    sake_kernel<<<NB, NT, smem_bytes>>>(
        g_h, g_x, b_in, We1, be1, be2, bh1, bh2, b_out, bn1, Wn2, bn2, out);
}

// round 17
// speedup vs baseline: 1.0534x; 1.0534x over previous
#include <cuda_runtime.h>

// SAKE GNN fully fused, one CTA per graph (B=512, M=32, H=128, L=2).
// R17: R14 structure (best: kh-split node GEMMs; 16 builder + 16 consumer
//      warps in pair phase) + R16's interleaved WF layout (B loads are a
//      single LDS.128). Drops R16's 3-way split (proven serialization loss).

#define NB 512
#define NT 1024
typedef unsigned int u32;
typedef unsigned short u16;

// global fragment buffer: 14 big Ws (16384 u32 each) + W_in (2048)
__device__ u32 g_wfrag[14 * 16384 + 2048];
#define WIN_BASE (14 * 16384)

// ---- shared memory layout (u32 word offsets) ----
#define O_HGH 0        // hg split: 32 x 68
#define O_HGL 2176
#define O_MIF 4352     // mi f32: 32 x 132
#define O_MJF 8576     // mj f32: 32 x 132
#define O_AGH 12800    // agg split: 32 x 68
#define O_AGL 14976
#define O_M1H 17152    // m1 split: 2 bufs x 32 x 68
#define O_M1L 21504
#define O_HTH 25856    // h input split: 32 x 8
#define O_HTL 26112
#define O_WF  26368    // W fragments interleaved: 8kt x 16nt x 32lane x 4
#define O_M2TH 42752   // m2 B-frag hi: 2 bufs x (128 cols x 20); also kh scratch
#define O_M2TL 47872
#define O_S   52992    // S selection: 2 bufs x (32 rows x 20)
#define O_D2  54912
#define O_EDGE 55936
#define O_WD  56960
#define O_BE2 57088
#define O_RMASK 57216
#define O_ROFF 57248
#define O_X   57280
#define O_RED 57376
#define O_NE  57392
#define SM_WORDS 57396

// named barrier ids
#define BFULL0 1
#define BEMPTY0 3
#define BCONS  5

#define BAR_SYNC(id, n)   asm volatile("bar.sync %0, %1;"   :: "r"(id), "r"(n) : "memory")
#define BAR_ARRIVE(id, n) asm volatile("bar.arrive %0, %1;" :: "r"(id), "r"(n) : "memory")

__device__ __forceinline__ float silu_f(float v) {
    return __fdividef(v, 1.0f + __expf(-v));
}
__device__ __forceinline__ u32 packbf(float x0, float x1) {
    u32 r;
    asm("cvt.rn.bf16x2.f32 %0, %1, %2;" : "=r"(r) : "f"(x1), "f"(x0));
    return r;
}
__device__ __forceinline__ void split2(float x0, float x1, u32& h, u32& l) {
    h = packbf(x0, x1);
    float r0 = x0 - __uint_as_float(h << 16);
    float r1 = x1 - __uint_as_float(h & 0xffff0000u);
    l = packbf(r0, r1);
}
__device__ __forceinline__ float2 ldpair(const u32* Xh, const u32* Xl, int idx) {
    u32 h = Xh[idx], l = Xl[idx];
    float2 v;
    v.x = __uint_as_float(h << 16) + __uint_as_float(l << 16);
    v.y = __uint_as_float(h & 0xffff0000u) + __uint_as_float(l & 0xffff0000u);
    return v;
}
__device__ __forceinline__ void stpair(u32* Xh, u32* Xl, int idx, float v0, float v1) {
    u32 h, l; split2(v0, v1, h, l);
    Xh[idx] = h; Xl[idx] = l;
}

__device__ __forceinline__ void mma4(float d[4], const u32 a[4], u32 b0, u32 b1) {
    asm volatile("mma.sync.aligned.m16n8k16.row.col.f32.bf16.bf16.f32 "
        "{%0,%1,%2,%3}, {%4,%5,%6,%7}, {%8,%9}, {%0,%1,%2,%3};"
        : "+f"(d[0]), "+f"(d[1]), "+f"(d[2]), "+f"(d[3])
        : "r"(a[0]), "r"(a[1]), "r"(a[2]), "r"(a[3]), "r"(b0), "r"(b1));
}

__device__ __forceinline__ u32 smaddr(const void* p) {
    return (u32)__cvta_generic_to_shared(p);
}
#define LDSM4(d, a) \
    asm volatile("ldmatrix.sync.aligned.m8n8.x4.shared.b16 {%0,%1,%2,%3}, [%4];" \
        : "=r"((d)[0]), "=r"((d)[1]), "=r"((d)[2]), "=r"((d)[3]) : "r"(a))

// 3-term GEMM, TWO n-tiles/warp, kt range [kt0,kt1); WF interleaved.
__device__ __forceinline__ void gemm_mma2n(const u32* Xh, const u32* Xl, int rs,
                                           const u32* sWF, int r0, int ntb,
                                           int lane, int kt0, int kt1,
                                           float D[2][4]) {
    int t = lane >> 3, rowin = lane & 7;
    int off = (r0 + ((t & 1) << 3) + rowin) * rs + ((t >> 1) << 2);
    u32 baseH = smaddr(Xh + off);
    u32 baseL = smaddr(Xl + off);
    #pragma unroll 1
    for (int kt = kt0; kt < kt1; kt++) {
        u32 ah[4], al[4];
        LDSM4(ah, baseH + kt * 32);
        LDSM4(al, baseL + kt * 32);
        #pragma unroll
        for (int t2 = 0; t2 < 2; t2++) {
            uint4 bb = *(const uint4*)(sWF + ((kt * 16 + ntb + t2) * 32 + lane) * 4);
            mma4(D[t2], ah, bb.x, bb.y);
            mma4(D[t2], ah, bb.z, bb.w);
            mma4(D[t2], al, bb.x, bb.y);
        }
    }
}

// combine kh halves via smem scratch; returns true if this warp owns epilogue.
__device__ __forceinline__ bool reduce_kh(float D[2][4], float* scr,
                                          int kh, int rtn, int ntp, int lane) {
    int base = (((rtn << 3) + ntp) * 32 + lane) * 8;
    if (kh) {
        *(float4*)&scr[base]     = make_float4(D[0][0], D[0][1], D[0][2], D[0][3]);
        *(float4*)&scr[base + 4] = make_float4(D[1][0], D[1][1], D[1][2], D[1][3]);
    }
    __syncthreads();
    if (!kh) {
        float4 p0 = *(const float4*)&scr[base];
        float4 p1 = *(const float4*)&scr[base + 4];
        D[0][0] += p0.x; D[0][1] += p0.y; D[0][2] += p0.z; D[0][3] += p0.w;
        D[1][0] += p1.x; D[1][1] += p1.y; D[1][2] += p1.z; D[1][3] += p1.w;
    }
    return !kh;
}

__device__ __forceinline__ void cp16(unsigned saddr, const void* g) {
    asm volatile("cp.async.cg.shared.global [%0], [%1], 16;" :: "r"(saddr), "l"(g));
}
#define CP_COMMIT() asm volatile("cp.async.commit_group;")
#define CP_WAIT0()  asm volatile("cp.async.wait_group 0;" ::: "memory")

__device__ __forceinline__ void stage_cp(const u32* __restrict__ g, u32* s,
                                         int nf4, int tid) {
    unsigned sa = (unsigned)__cvta_generic_to_shared(s);
    for (int v = tid; v < nf4; v += NT)
        cp16(sa + v * 16, g + v * 4);
}
__device__ __forceinline__ void stage_W(const u32* __restrict__ F, u32* WF, int tid) {
    stage_cp(F, WF, 4096, tid);
    CP_COMMIT();
}

// write one f32 value into the hi/lo B-fragment m2 buffers at (col c, edge r)
__device__ __forceinline__ void write_m2t(u32* M2THb, u32* M2TLb, int c, int r, float v) {
    u32 hp = packbf(v, 0.0f);
    float hf = __uint_as_float(hp << 16);
    u32 lp = packbf(v - hf, 0.0f);
    int wi = (c * 20 + (r >> 1)) * 2 + (r & 1);
    ((u16*)M2THb)[wi] = (u16)hp;
    ((u16*)M2TLb)[wi] = (u16)lp;
}

// builder: 512 threads, 16 threads/edge, 8 cols each
__device__ __forceinline__ void build_chunk_p(int e0, int nE, const int* s_edge,
                                              const float* s_d2, const float* miF,
                                              const float* mjF, const float* s_wd,
                                              u32* M1Hb, u32* M1Lb, int tid) {
    int e = tid >> 4;            // 0..31
    int cq = (tid & 15) * 8;     // 8 cols
    int ee = e0 + e;
    int ij = s_edge[ee < nE ? ee : nE - 1];
    int i = ij >> 5, j = ij & 31;
    float dd = s_d2[ij];
    u32 hb[4], lb[4];
    #pragma unroll
    for (int q = 0; q < 2; q++) {
        float4 a = *(const float4*)&miF[i * 132 + cq + 4 * q];
        float4 bb = *(const float4*)&mjF[j * 132 + cq + 4 * q];
        float4 w = *(const float4*)&s_wd[cq + 4 * q];
        float v0 = silu_f(a.x + bb.x + dd * w.x);
        float v1 = silu_f(a.y + bb.y + dd * w.y);
        float v2 = silu_f(a.z + bb.z + dd * w.z);
        float v3 = silu_f(a.w + bb.w + dd * w.w);
        split2(v0, v1, hb[2 * q], lb[2 * q]);
        split2(v2, v3, hb[2 * q + 1], lb[2 * q + 1]);
    }
    *(uint4*)&M1Hb[e * 68 + (cq >> 1)] = make_uint4(hb[0], hb[1], hb[2], hb[3]);
    *(uint4*)&M1Lb[e * 68 + (cq >> 1)] = make_uint4(lb[0], lb[1], lb[2], lb[3]);
}

// build S selection matrix for one chunk (tids 0..511 of the calling group)
__device__ __forceinline__ void build_S(int e0, int nE, const int* s_edge,
                                        u32* Sb, int tid) {
    int i = tid >> 4, ep = tid & 15;
    int ea = e0 + 2 * ep, eb = ea + 1;
    int ia = (ea < nE) ? (s_edge[ea] >> 5) : -1;
    int ib = (eb < nE) ? (s_edge[eb] >> 5) : -1;
    u32 val = (ia == i ? 0x00003F80u : 0u) | (ib == i ? 0x3F800000u : 0u);
    Sb[i * 20 + ep] = val;
}

// consumer agg: Dagg[2][4] += S @ (m2h + m2l), 2 n-tiles
__device__ __forceinline__ void agg_mma2(const u32* Sp, const u32* m2h,
                                         const u32* m2l, int rt, int ntb,
                                         int lane, float Dagg[2][4]) {
    int t = lane >> 3, rowin = lane & 7;
    u32 baseS = smaddr(Sp + (rt * 16 + ((t & 1) << 3) + rowin) * 20 + ((t >> 1) << 2));
    #pragma unroll
    for (int kt = 0; kt < 2; kt++) {
        u32 a[4];
        LDSM4(a, baseS + kt * 32);
        #pragma unroll
        for (int t2 = 0; t2 < 2; t2++) {
            int cB = (ntb + t2) * 8 + (lane >> 2);
            const u32* bh = m2h + cB * 20 + kt * 8 + (lane & 3);
            const u32* bl = m2l + cB * 20 + kt * 8 + (lane & 3);
            mma4(Dagg[t2], a, bh[0], bh[4]);
            mma4(Dagg[t2], a, bl[0], bl[4]);
        }
    }
}

// ================= prep kernel: weights -> interleaved fragment layout ======
__global__ void prep_kernel(const float* __restrict__ We1,
                            const float* __restrict__ We2,
                            const float* __restrict__ Wh1,
                            const float* __restrict__ Wh2,
                            const float* __restrict__ W_out,
                            const float* __restrict__ Wn1,
                            const float* __restrict__ W_in) {
    int y = blockIdx.y;
    int u = blockIdx.x * 256 + threadIdx.x;
    if (y < 14) {
        const float* src;
        if (y < 12) {
            int l = y / 6, w = y % 6;
            switch (w) {
                case 0: src = We1 + l * 257 * 128; break;
                case 1: src = We1 + l * 257 * 128 + 16384; break;
                case 2: src = We2 + l * 16384; break;
                case 3: src = Wh1 + l * 32768; break;
                case 4: src = Wh1 + l * 32768 + 16384; break;
                default: src = Wh2 + l * 16384; break;
            }
        } else {
            src = (y == 12) ? W_out : Wn1;
        }
        int p = u >> 7, c = u & 127;
        float w0 = src[(2 * p) * 128 + c];
        float w1 = src[(2 * p + 1) * 128 + c];
        int kt = p >> 3, pr = p & 7;
        int cpp = pr & 3, reg = pr >> 2;
        int lane = (c & 7) * 4 + cpp;
        int nt = c >> 3;
        int dst = y * 16384 + ((kt * 16 + nt) * 32 + lane) * 4 + reg;
        u32 h, l2; split2(w0, w1, h, l2);
        g_wfrag[dst] = h;
        g_wfrag[dst + 2] = l2;
    } else {
        if (u >= 1024) return;
        int p = u >> 7, c = u & 127;
        float w0 = W_in[(2 * p) * 128 + c];
        float w1 = W_in[(2 * p + 1) * 128 + c];
        int cpp = p & 3, reg = p >> 2;
        int lane = (c & 7) * 4 + cpp;
        int nt = c >> 3;
        int dst = WIN_BASE + ((nt * 32 + lane) * 4 + reg);
        u32 h, l2; split2(w0, w1, h, l2);
        g_wfrag[dst] = h;
        g_wfrag[dst + 2] = l2;
    }
}

// ================================ main kernel ================================
__global__ void __launch_bounds__(NT, 1)
sake_kernel(const float* __restrict__ g_h, const float* __restrict__ g_x,
            const float* __restrict__ b_in,
            const float* __restrict__ We1, const float* __restrict__ be1,
            const float* __restrict__ be2,
            const float* __restrict__ bh1, const float* __restrict__ bh2,
            const float* __restrict__ b_out,
            const float* __restrict__ bn1,
            const float* __restrict__ Wn2, const float* __restrict__ bn2,
            float* __restrict__ g_out)
{
    extern __shared__ u32 smu[];
    u32* HGH = smu + O_HGH;  u32* HGL = smu + O_HGL;
    float* miF = (float*)(smu + O_MIF);
    float* mjF = (float*)(smu + O_MJF);
    u32* AGH = smu + O_AGH;  u32* AGL = smu + O_AGL;
    u32* M1H = smu + O_M1H;  u32* M1L = smu + O_M1L;
    u32* HTH = smu + O_HTH;  u32* HTL = smu + O_HTL;
    u32* WF  = smu + O_WF;
    u32* M2TH = smu + O_M2TH;
    u32* M2TL = smu + O_M2TL;
    float* scrF = (float*)(smu + O_M2TH);   // kh reduction scratch (node GEMMs)
    u32* Sbuf = smu + O_S;
    float* s_d2   = (float*)(smu + O_D2);
    int*   s_edge = (int*)(smu + O_EDGE);
    float* s_wd   = (float*)(smu + O_WD);
    float* s_be2  = (float*)(smu + O_BE2);
    u32*   s_rmask = smu + O_RMASK;
    int*   s_roff  = (int*)(smu + O_ROFF);
    float* s_x    = (float*)(smu + O_X);
    float* s_red  = (float*)(smu + O_RED);
    int*   s_ne   = (int*)(smu + O_NE);

    const int tid  = threadIdx.x;
    const int warp = tid >> 5;          // 0..31
    const int lane = tid & 31;
    const int gid  = lane >> 2;
    const int tig  = lane & 3;
    const int b    = blockIdx.x;
    // node-GEMM mapping: (kh, rtn, ntp)
    const int kh   = warp & 1;
    const int rtn  = (warp >> 1) & 1;
    const int ntp  = warp >> 2;         // 0..7
    const int ntbN = ntp * 2;
    const int rr0  = rtn * 16 + gid;
    const int kt0  = kh ? 4 : 0;
    const int kt1  = kh ? 8 : 4;

    // ---- prologue: x, split h, stage W_in frags ----
    if (tid < 96) s_x[tid] = g_x[b * 96 + tid];
    if (tid < 256) {
        int r = tid >> 3, cp = tid & 7;
        float2 hv = *(const float2*)&g_h[b * 512 + r * 16 + cp * 2];
        u32 h, l; split2(hv.x, hv.y, h, l);
        HTH[r * 8 + cp] = h; HTL[r * 8 + cp] = l;
    }
    stage_cp(g_wfrag + WIN_BASE, WF, 512, tid);
    CP_COMMIT();
    __syncthreads();

    // ---- d2 ----
    for (int p = tid; p < 1024; p += NT) {
        int i = p >> 5, j = p & 31;
        float dx = s_x[i * 3 + 0] - s_x[j * 3 + 0];
        float dy = s_x[i * 3 + 1] - s_x[j * 3 + 1];
        float dz = s_x[i * 3 + 2] - s_x[j * 3 + 2];
        s_d2[p] = dx * dx + dy * dy + dz * dz;
    }
    __syncthreads();

    // ---- adjacency masks: warp w owns node w ----
    {
        bool adj = (s_d2[warp * 32 + lane] < 1.0f) && (lane != warp);
        unsigned m = __ballot_sync(0xffffffffu, adj);
        if (lane == 0) s_rmask[warp] = m;
    }
    CP_WAIT0();
    __syncthreads();

    // ---- hg = h @ W_in + b_in (kh0 warps only; 1 kt) ----
    if (!kh) {
        float D[2][4] = {};
        gemm_mma2n(HTH, HTL, 8, WF, rtn * 16, ntbN, lane, 0, 1, D);
        #pragma unroll
        for (int t2 = 0; t2 < 2; t2++) {
            int cc = (ntbN + t2) * 8 + 2 * tig;
            float b0 = b_in[cc], b1 = b_in[cc + 1];
            stpair(HGH, HGL, rr0 * 68 + (cc >> 1),       D[t2][0] + b0, D[t2][1] + b1);
            stpair(HGH, HGL, (rr0 + 8) * 68 + (cc >> 1), D[t2][2] + b0, D[t2][3] + b1);
        }
    }

    // ---- edge-list scan ----
    __syncthreads();
    if (warp == 0) {
        unsigned m = s_rmask[lane];
        int c = __popc(m);
        int inc = c;
        #pragma unroll
        for (int d = 1; d < 32; d <<= 1) {
            int n = __shfl_up_sync(0xffffffffu, inc, d);
            if (lane >= d) inc += n;
        }
        s_roff[lane] = inc - c;
        if (lane == 31) *s_ne = inc;
    }
    __syncthreads();
    {
        unsigned m = s_rmask[warp];
        if ((m >> lane) & 1u) {
            int pos = s_roff[warp] + __popc(m & ((1u << lane) - 1u));
            s_edge[pos] = (warp << 5) | lane;
        }
    }
    __syncthreads();
    const int nE = *s_ne;
    const int nCh = (nE + 31) >> 5;

    // ---- layers ----
    #pragma unroll 1
    for (int l = 0; l < 2; l++) {
        const u32* F_e1a = g_wfrag + (l * 6 + 0) * 16384;
        const u32* F_e1b = g_wfrag + (l * 6 + 1) * 16384;
        const u32* F_e2  = g_wfrag + (l * 6 + 2) * 16384;
        const u32* F_h1a = g_wfrag + (l * 6 + 3) * 16384;
        const u32* F_h1b = g_wfrag + (l * 6 + 4) * 16384;
        const u32* F_h2  = g_wfrag + (l * 6 + 5) * 16384;
        const float* We1l = We1 + l * (257 * 128);

        // mi = hg @ We1a + be1 -> miF
        stage_W(F_e1a, WF, tid); CP_WAIT0(); __syncthreads();
        {
            float D[2][4] = {};
            gemm_mma2n(HGH, HGL, 68, WF, rtn * 16, ntbN, lane, kt0, kt1, D);
            if (reduce_kh(D, scrF, kh, rtn, ntp, lane)) {
                #pragma unroll
                for (int t2 = 0; t2 < 2; t2++) {
                    int cc = (ntbN + t2) * 8 + 2 * tig;
                    float b0 = be1[l * 128 + cc], b1 = be1[l * 128 + cc + 1];
                    *(float2*)&miF[rr0 * 132 + cc]       = make_float2(D[t2][0] + b0, D[t2][1] + b1);
                    *(float2*)&miF[(rr0 + 8) * 132 + cc] = make_float2(D[t2][2] + b0, D[t2][3] + b1);
                }
            }
        }
        __syncthreads();

        // mj = hg @ We1b -> mjF
        stage_W(F_e1b, WF, tid); CP_WAIT0(); __syncthreads();
        {
            float D[2][4] = {};
            gemm_mma2n(HGH, HGL, 68, WF, rtn * 16, ntbN, lane, kt0, kt1, D);
            if (reduce_kh(D, scrF, kh, rtn, ntp, lane)) {
                #pragma unroll
                for (int t2 = 0; t2 < 2; t2++) {
                    int cc = (ntbN + t2) * 8 + 2 * tig;
                    *(float2*)&mjF[rr0 * 132 + cc]       = make_float2(D[t2][0], D[t2][1]);
                    *(float2*)&mjF[(rr0 + 8) * 132 + cc] = make_float2(D[t2][2], D[t2][3]);
                }
            }
        }
        __syncthreads();

        // stage We2; wd, be2
        stage_W(F_e2, WF, tid);
        if (tid < 128) {
            s_wd[tid]  = We1l[256 * 128 + tid];
            s_be2[tid] = be2[l * 128 + tid];
        }
        CP_WAIT0();
        __syncthreads();

        // ---- pair phase: 16 builders / 16 consumers (R14 pipeline) ----
        float Dagg[2][4] = {};
        if (nCh > 0) {
            if (warp < 16) {
                // BUILDERS: m1 + S chunks
                #pragma unroll 1
                for (int c = 0; c < nCh; c++) {
                    const int buf = c & 1;
                    if (c >= 2) BAR_SYNC(BEMPTY0 + buf, 1024);
                    build_chunk_p(c * 32, nE, s_edge, s_d2, miF, mjF, s_wd,
                                  M1H + buf * 2176, M1L + buf * 2176, tid);
                    build_S(c * 32, nE, s_edge, Sbuf + buf * 640, tid);
                    BAR_ARRIVE(BFULL0 + buf, 1024);
                }
            } else {
                // CONSUMERS: pair GEMM (2 n-tiles) + agg
                const int cw   = warp - 16;
                const int crt  = cw & 1;
                const int cntb = (cw >> 1) * 2;
                const int cr0  = crt * 16 + gid;
                #pragma unroll 1
                for (int c = 0; c < nCh; c++) {
                    const int buf = c & 1;
                    BAR_SYNC(BFULL0 + buf, 1024);
                    float D[2][4] = {};
                    gemm_mma2n(M1H + buf * 2176, M1L + buf * 2176, 68, WF,
                               crt * 16, cntb, lane, 0, 8, D);
                    u32* m2h = M2TH + buf * 2560;
                    u32* m2l = M2TL + buf * 2560;
                    #pragma unroll
                    for (int t2 = 0; t2 < 2; t2++) {
                        int cc = (cntb + t2) * 8 + 2 * tig;
                        float b0 = s_be2[cc], b1 = s_be2[cc + 1];
                        write_m2t(m2h, m2l, cc,     cr0,     silu_f(D[t2][0] + b0));
                        write_m2t(m2h, m2l, cc + 1, cr0,     silu_f(D[t2][1] + b1));
                        write_m2t(m2h, m2l, cc,     cr0 + 8, silu_f(D[t2][2] + b0));
                        write_m2t(m2h, m2l, cc + 1, cr0 + 8, silu_f(D[t2][3] + b1));
                    }
                    BAR_SYNC(BCONS, 512);
                    agg_mma2(Sbuf + buf * 640, m2h, m2l, crt, cntb, lane, Dagg);
                    if (c < nCh - 2) BAR_ARRIVE(BEMPTY0 + buf, 1024);
                }
            }
        }
        __syncthreads();

        // consumers write agg registers -> AG split arrays; stage Wh1a (all)
        stage_W(F_h1a, WF, tid);
        if (warp >= 16) {
            const int cw   = warp - 16;
            const int crt  = cw & 1;
            const int cntb = (cw >> 1) * 2;
            const int cr0  = crt * 16 + gid;
            #pragma unroll
            for (int t2 = 0; t2 < 2; t2++) {
                int cc = (cntb + t2) * 8 + 2 * tig;
                stpair(AGH, AGL, cr0 * 68 + (cc >> 1),       Dagg[t2][0], Dagg[t2][1]);
                stpair(AGH, AGL, (cr0 + 8) * 68 + (cc >> 1), Dagg[t2][2], Dagg[t2][3]);
            }
        }
        CP_WAIT0();
        __syncthreads();

        // u = silu(hg @ Wh1a + agg @ Wh1b + bh1) -> M1 (split, buf0)
        {
            float D[2][4] = {};
            gemm_mma2n(HGH, HGL, 68, WF, rtn * 16, ntbN, lane, kt0, kt1, D);
            __syncthreads();
            stage_W(F_h1b, WF, tid);
            CP_WAIT0();
            __syncthreads();
            gemm_mma2n(AGH, AGL, 68, WF, rtn * 16, ntbN, lane, kt0, kt1, D);
            if (reduce_kh(D, scrF, kh, rtn, ntp, lane)) {
                #pragma unroll
                for (int t2 = 0; t2 < 2; t2++) {
                    int cc = (ntbN + t2) * 8 + 2 * tig;
                    float b0 = bh1[l * 128 + cc], b1 = bh1[l * 128 + cc + 1];
                    stpair(M1H, M1L, rr0 * 68 + (cc >> 1),
                           silu_f(D[t2][0] + b0), silu_f(D[t2][1] + b1));
                    stpair(M1H, M1L, (rr0 + 8) * 68 + (cc >> 1),
                           silu_f(D[t2][2] + b0), silu_f(D[t2][3] + b1));
                }
            }
        }
        __syncthreads();

        // hg += u @ Wh2 + bh2
        stage_W(F_h2, WF, tid); CP_WAIT0(); __syncthreads();
        {
            float D[2][4] = {};
            gemm_mma2n(M1H, M1L, 68, WF, rtn * 16, ntbN, lane, kt0, kt1, D);
            if (reduce_kh(D, scrF, kh, rtn, ntp, lane)) {
                #pragma unroll
                for (int t2 = 0; t2 < 2; t2++) {
                    int cc = (ntbN + t2) * 8 + 2 * tig;
                    float b0 = bh2[l * 128 + cc], b1 = bh2[l * 128 + cc + 1];
                    float2 h0 = ldpair(HGH, HGL, rr0 * 68 + (cc >> 1));
                    stpair(HGH, HGL, rr0 * 68 + (cc >> 1),
                           h0.x + D[t2][0] + b0, h0.y + D[t2][1] + b1);
                    float2 h1 = ldpair(HGH, HGL, (rr0 + 8) * 68 + (cc >> 1));
                    stpair(HGH, HGL, (rr0 + 8) * 68 + (cc >> 1),
                           h1.x + D[t2][2] + b0, h1.y + D[t2][3] + b1);
                }
            }
        }
        __syncthreads();
    }

    // ---- head: ho = hg @ W_out + b_out -> M1 (split, buf0) ----
    stage_W(g_wfrag + 12 * 16384, WF, tid); CP_WAIT0(); __syncthreads();
    {
        float D[2][4] = {};
        gemm_mma2n(HGH, HGL, 68, WF, rtn * 16, ntbN, lane, kt0, kt1, D);
        if (reduce_kh(D, scrF, kh, rtn, ntp, lane)) {
            #pragma unroll
            for (int t2 = 0; t2 < 2; t2++) {
                int cc = (ntbN + t2) * 8 + 2 * tig;
                float b0 = b_out[cc], b1 = b_out[cc + 1];
                stpair(M1H, M1L, rr0 * 68 + (cc >> 1),       D[t2][0] + b0, D[t2][1] + b1);
                stpair(M1H, M1L, (rr0 + 8) * 68 + (cc >> 1), D[t2][2] + b0, D[t2][3] + b1);
            }
        }
    }
    __syncthreads();

    // t1 = silu(ho @ Wn1 + bn1) -> miF (f32)
    stage_W(g_wfrag + 13 * 16384, WF, tid); CP_WAIT0(); __syncthreads();
    {
        float D[2][4] = {};
        gemm_mma2n(M1H, M1L, 68, WF, rtn * 16, ntbN, lane, kt0, kt1, D);
        if (reduce_kh(D, scrF, kh, rtn, ntp, lane)) {
            #pragma unroll
            for (int t2 = 0; t2 < 2; t2++) {
                int cc = (ntbN + t2) * 8 + 2 * tig;
                float b0 = bn1[cc], b1 = bn1[cc + 1];
                *(float2*)&miF[rr0 * 132 + cc] =
                    make_float2(silu_f(D[t2][0] + b0), silu_f(D[t2][1] + b1));
                *(float2*)&miF[(rr0 + 8) * 132 + cc] =
                    make_float2(silu_f(D[t2][2] + b0), silu_f(D[t2][3] + b1));
            }
        }
    }
    __syncthreads();

    // ---- out[b] = (colsum t1) . Wn2 + 32*bn2 ----
    float part = 0.0f;
    if (tid < 128) {
        int c = tid;
        float s = 0.0f;
        #pragma unroll 1
        for (int i = 0; i < 32; i++) s += miF[i * 132 + c];
        part = s * Wn2[c];
    }
    #pragma unroll
    for (int off = 16; off > 0; off >>= 1)
        part += __shfl_down_sync(0xffffffffu, part, off);
    if (warp < 4 && lane == 0) s_red[warp] = part;
    __syncthreads();
    if (tid == 0)
        g_out[b] = s_red[0] + s_red[1] + s_red[2] + s_red[3] + 32.0f * bn2[0];
}

extern "C" void kernel_launch(void* const* d_in, const int* in_sizes, int n_in,
                              void* d_out, int out_size) {
    const float* g_h   = (const float*)d_in[0];
    const float* g_x   = (const float*)d_in[1];
    const float* W_in  = (const float*)d_in[3];
    const float* b_in  = (const float*)d_in[4];
    const float* We1   = (const float*)d_in[5];
    const float* be1   = (const float*)d_in[6];
    const float* We2   = (const float*)d_in[7];
    const float* be2   = (const float*)d_in[8];
    const float* Wh1   = (const float*)d_in[9];
    const float* bh1   = (const float*)d_in[10];
    const float* Wh2   = (const float*)d_in[11];
    const float* bh2   = (const float*)d_in[12];
    const float* W_out = (const float*)d_in[13];
    const float* b_out = (const float*)d_in[14];
    const float* Wn1   = (const float*)d_in[15];
    const float* bn1   = (const float*)d_in[16];
    const float* Wn2   = (const float*)d_in[17];
    const float* bn2   = (const float*)d_in[18];
    float* out = (float*)d_out;

    prep_kernel<<<dim3(32, 15), 256>>>(We1, We2, Wh1, Wh2, W_out, Wn1, W_in);

    const int smem_bytes = SM_WORDS * 4;
    cudaFuncSetAttribute(sake_kernel, cudaFuncAttributeMaxDynamicSharedMemorySize,
                         smem_bytes);
    sake_kernel<<<NB, NT, smem_bytes>>>(
        g_h, g_x, b_in, We1, be1, be2, bh1, bh2, b_out, bn1, Wn2, bn2, out);
}